// round 14
// baseline (speedup 1.0000x reference)
#include <cuda_runtime.h>
#include <math.h>

#define BB 4
#define NN 2048
#define DD 1024
#define HH 64
#define M_TOT (BB*NN)
#define SPLITS 8
#define ZSPLITS 8

static __device__ float g_q[M_TOT*HH];
static __device__ float g_k[M_TOT*HH];
static __device__ float g_v[M_TOT*HH];
static __device__ float g_Zp[M_TOT*ZSPLITS];       // partial row sums
static __device__ float g_rZ[M_TOT];               // 1/rowsum
static __device__ float g_part[SPLITS][M_TOT*HH];  // split-K partials for PV

// ---------------------------------------------------------------------------
// TF32 helpers
// ---------------------------------------------------------------------------
__device__ __forceinline__ unsigned f2tf(float f) {
    unsigned u; asm("cvt.rna.tf32.f32 %0, %1;" : "=r"(u) : "f"(f)); return u;
}
__device__ __forceinline__ void mma8(float c[4],
                                     unsigned a0, unsigned a1, unsigned a2, unsigned a3,
                                     unsigned b0, unsigned b1) {
    asm volatile(
        "mma.sync.aligned.m16n8k8.row.col.f32.tf32.tf32.f32 "
        "{%0,%1,%2,%3}, {%4,%5,%6,%7}, {%8,%9}, {%0,%1,%2,%3};"
        : "+f"(c[0]), "+f"(c[1]), "+f"(c[2]), "+f"(c[3])
        : "r"(a0), "r"(a1), "r"(a2), "r"(a3), "r"(b0), "r"(b1));
}

// ---------------------------------------------------------------------------
// Kernel 1: fused QKV projection, tf32 MMA, register-prefetched k-stages.
// ---------------------------------------------------------------------------
__global__ __launch_bounds__(256) void qkv_kernel(
    const float* __restrict__ x,
    const float* __restrict__ Wq, const float* __restrict__ bq,
    const float* __restrict__ Wk, const float* __restrict__ bk,
    const float* __restrict__ Wv, const float* __restrict__ bv)
{
    __shared__ unsigned as_[64][36];
    __shared__ unsigned bs_[32][200];

    const int tid = threadIdx.x;
    const int wid = tid >> 5, lane = tid & 31;
    const int group = lane >> 2, tig = lane & 3;
    const int warp_m = wid >> 2;
    const int warp_n = wid & 3;
    const int row0 = blockIdx.x * 64;

    float acc[2][6][4] = {};

    // prefetch buffers: x tile (2 f4), W tiles (3 proj x 2 f4)
    float4 xbuf[2], wbuf[3][2];
    {
        #pragma unroll
        for (int e = 0; e < 2; e++) {
            int id = tid + e * 256;
            int r = id >> 3, c4 = id & 7;
            xbuf[e] = *(const float4*)&x[(size_t)(row0 + r) * DD + c4 * 4];
        }
        #pragma unroll
        for (int p = 0; p < 3; p++) {
            const float* W = (p == 0) ? Wq : (p == 1) ? Wk : Wv;
            #pragma unroll
            for (int e = 0; e < 2; e++) {
                int id = tid + e * 256;
                int r = id >> 4, c4 = id & 15;
                wbuf[p][e] = *(const float4*)&W[(size_t)r * HH + c4 * 4];
            }
        }
    }

    for (int kt = 0; kt < DD; kt += 32) {
        // ---- STS from prefetched registers ----
        #pragma unroll
        for (int e = 0; e < 2; e++) {
            int id = tid + e * 256;
            int r = id >> 3, c4 = id & 7;
            float4 v = xbuf[e];
            as_[r][c4*4+0] = f2tf(v.x); as_[r][c4*4+1] = f2tf(v.y);
            as_[r][c4*4+2] = f2tf(v.z); as_[r][c4*4+3] = f2tf(v.w);
        }
        #pragma unroll
        for (int p = 0; p < 3; p++) {
            #pragma unroll
            for (int e = 0; e < 2; e++) {
                int id = tid + e * 256;
                int r = id >> 4, c4 = id & 15;
                float4 v = wbuf[p][e];
                bs_[r][p*64 + c4*4+0] = f2tf(v.x); bs_[r][p*64 + c4*4+1] = f2tf(v.y);
                bs_[r][p*64 + c4*4+2] = f2tf(v.z); bs_[r][p*64 + c4*4+3] = f2tf(v.w);
            }
        }
        __syncthreads();

        // ---- prefetch next k-stage (overlaps MMAs) ----
        if (kt + 32 < DD) {
            const int ktn = kt + 32;
            #pragma unroll
            for (int e = 0; e < 2; e++) {
                int id = tid + e * 256;
                int r = id >> 3, c4 = id & 7;
                xbuf[e] = *(const float4*)&x[(size_t)(row0 + r) * DD + ktn + c4 * 4];
            }
            #pragma unroll
            for (int p = 0; p < 3; p++) {
                const float* W = (p == 0) ? Wq : (p == 1) ? Wk : Wv;
                #pragma unroll
                for (int e = 0; e < 2; e++) {
                    int id = tid + e * 256;
                    int r = id >> 4, c4 = id & 15;
                    wbuf[p][e] = *(const float4*)&W[(size_t)(ktn + r) * HH + c4 * 4];
                }
            }
        }

        #pragma unroll
        for (int kk = 0; kk < 4; kk++) {
            const int k = kk * 8;
            unsigned af[2][4];
            #pragma unroll
            for (int mi = 0; mi < 2; mi++) {
                int r = warp_m * 32 + mi * 16 + group;
                af[mi][0] = as_[r][k + tig];     af[mi][1] = as_[r + 8][k + tig];
                af[mi][2] = as_[r][k + tig + 4]; af[mi][3] = as_[r + 8][k + tig + 4];
            }
            unsigned bf[6][2];
            #pragma unroll
            for (int ni = 0; ni < 6; ni++) {
                int c = warp_n * 48 + ni * 8 + group;
                bf[ni][0] = bs_[k + tig][c];
                bf[ni][1] = bs_[k + tig + 4][c];
            }
            #pragma unroll
            for (int mi = 0; mi < 2; mi++)
                #pragma unroll
                for (int ni = 0; ni < 6; ni++)
                    mma8(acc[mi][ni], af[mi][0], af[mi][1], af[mi][2], af[mi][3],
                         bf[ni][0], bf[ni][1]);
        }
        __syncthreads();
    }

    #pragma unroll
    for (int mi = 0; mi < 2; mi++) {
        int r = row0 + warp_m * 32 + mi * 16 + group;
        #pragma unroll
        for (int ni = 0; ni < 6; ni++) {
            int col = warp_n * 48 + ni * 8 + 2 * tig;
            int p = col >> 6, c = col & 63;
            const float* bias = (p == 0) ? bq : (p == 1) ? bk : bv;
            float* outp      = (p == 0) ? g_q : (p == 1) ? g_k : g_v;
            float b0 = bias[c], b1 = bias[c + 1];
            *(float2*)&outp[(size_t)r * HH + c] =
                make_float2(acc[mi][ni][0] + b0, acc[mi][ni][1] + b1);
            *(float2*)&outp[(size_t)(r + 8) * HH + c] =
                make_float2(acc[mi][ni][2] + b0, acc[mi][ni][3] + b1);
        }
    }
}

// ---------------------------------------------------------------------------
// Kernel 2: zsum with register-prefetched K tiles.
// Warps 2(j) x 4(i); warp tile 64j x 32i. isplit 8-way.
// ---------------------------------------------------------------------------
#define ZS_SMEM ((2 * 128 * 68 + 4 * 128) * 4)
__global__ __launch_bounds__(256) void zsum_kernel()
{
    const int tj = blockIdx.x, isplit = blockIdx.y, b = blockIdx.z;

    extern __shared__ unsigned dynsm[];
    unsigned (*qs_)[68] = (unsigned(*)[68])dynsm;              // [j][h]
    unsigned (*ks_)[68] = (unsigned(*)[68])(dynsm + 128 * 68); // [i][h]
    float* zsh = (float*)(dynsm + 2 * 128 * 68);               // [4 warpi][128 j]

    const int tid = threadIdx.x;
    const int wid = tid >> 5, lane = tid & 31;
    const int group = lane >> 2, tig = lane & 3;
    const int warpj = wid >> 2;         // 0..1 (64 j each)
    const int warpi = wid & 3;          // 0..3 (32 i each)
    const int j0 = tj * 128;

    const float* qp = g_q + ((size_t)b * NN + j0) * HH;
    #pragma unroll
    for (int e = 0; e < 8; e++) {
        int id = tid + e * 256;                    // 2048 float4s
        int r = id >> 4, c4 = id & 15;
        float4 q4 = *(const float4*)&qp[(size_t)r * HH + c4 * 4];
        qs_[r][c4*4+0]=f2tf(q4.x); qs_[r][c4*4+1]=f2tf(q4.y);
        qs_[r][c4*4+2]=f2tf(q4.z); qs_[r][c4*4+3]=f2tf(q4.w);
    }

    const int count = 16 - tj;
    const int chunk = (count + ZSPLITS - 1) / ZSPLITS;
    const int it0 = tj + isplit * chunk;
    const int it1 = min(16, it0 + chunk);

    float zacc[4][2] = {};

    // prefetch first K tile (8 f4/thread)
    float4 kbuf[8];
    if (it0 < it1) {
        const float* kp = g_k + ((size_t)b * NN + it0 * 128) * HH;
        #pragma unroll
        for (int e = 0; e < 8; e++) {
            int id = tid + e * 256;
            int r = id >> 4, c4 = id & 15;
            kbuf[e] = *(const float4*)&kp[(size_t)r * HH + c4 * 4];
        }
    }

    for (int it = it0; it < it1; it++) {
        // ---- STS from prefetched registers ----
        #pragma unroll
        for (int e = 0; e < 8; e++) {
            int id = tid + e * 256;
            int r = id >> 4, c4 = id & 15;
            float4 k4 = kbuf[e];
            ks_[r][c4*4+0]=f2tf(k4.x); ks_[r][c4*4+1]=f2tf(k4.y);
            ks_[r][c4*4+2]=f2tf(k4.z); ks_[r][c4*4+3]=f2tf(k4.w);
        }
        __syncthreads();           // also covers the qs_ stores (first iter)

        // ---- prefetch next K tile (overlaps MMA + exp) ----
        if (it + 1 < it1) {
            const float* kp = g_k + ((size_t)b * NN + (it + 1) * 128) * HH;
            #pragma unroll
            for (int e = 0; e < 8; e++) {
                int id = tid + e * 256;
                int r = id >> 4, c4 = id & 15;
                kbuf[e] = *(const float4*)&kp[(size_t)r * HH + c4 * 4];
            }
        }

        float acc[4][4][4] = {};
        #pragma unroll
        for (int kk = 0; kk < 8; kk++) {
            const int k = kk * 8;
            unsigned af[4][4];
            #pragma unroll
            for (int mi = 0; mi < 4; mi++) {
                int r = warpj * 64 + mi * 16 + group;
                af[mi][0] = qs_[r][k + tig];     af[mi][1] = qs_[r + 8][k + tig];
                af[mi][2] = qs_[r][k + tig + 4]; af[mi][3] = qs_[r + 8][k + tig + 4];
            }
            unsigned bf[4][2];
            #pragma unroll
            for (int ni = 0; ni < 4; ni++) {
                int c = warpi * 32 + ni * 8 + group;
                bf[ni][0] = ks_[c][k + tig];
                bf[ni][1] = ks_[c][k + tig + 4];
            }
            #pragma unroll
            for (int mi = 0; mi < 4; mi++)
                #pragma unroll
                for (int ni = 0; ni < 4; ni++)
                    mma8(acc[mi][ni], af[mi][0], af[mi][1], af[mi][2], af[mi][3],
                         bf[ni][0], bf[ni][1]);
        }

        const int i0 = it * 128;
        #pragma unroll
        for (int mi = 0; mi < 4; mi++) {
            #pragma unroll
            for (int ni = 0; ni < 4; ni++) {
                int jA = j0 + warpj * 64 + mi * 16 + group;
                int iA = i0 + warpi * 32 + ni * 8 + 2 * tig;
                float v00 = acc[mi][ni][0], v01 = acc[mi][ni][1];
                float v10 = acc[mi][ni][2], v11 = acc[mi][ni][3];
                float e00 = (iA     < jA     || v00 == 0.0f) ? 0.0f : __expf(v00 * 0.125f);
                float e01 = (iA + 1 < jA     || v01 == 0.0f) ? 0.0f : __expf(v01 * 0.125f);
                float e10 = (iA     < jA + 8 || v10 == 0.0f) ? 0.0f : __expf(v10 * 0.125f);
                float e11 = (iA + 1 < jA + 8 || v11 == 0.0f) ? 0.0f : __expf(v11 * 0.125f);
                zacc[mi][0] += e00 + e01;
                zacc[mi][1] += e10 + e11;
            }
        }
        __syncthreads();           // ks_ reads done before next iter's STS
    }

    #pragma unroll
    for (int mi = 0; mi < 4; mi++) {
        float s0 = zacc[mi][0], s1 = zacc[mi][1];
        s0 += __shfl_xor_sync(0xffffffffu, s0, 1);
        s0 += __shfl_xor_sync(0xffffffffu, s0, 2);
        s1 += __shfl_xor_sync(0xffffffffu, s1, 1);
        s1 += __shfl_xor_sync(0xffffffffu, s1, 2);
        zacc[mi][0] = s0; zacc[mi][1] = s1;
    }
    __syncthreads();
    if (tig == 0) {
        #pragma unroll
        for (int mi = 0; mi < 4; mi++) {
            int jl = warpj * 64 + mi * 16 + group;
            zsh[warpi * 128 + jl]     = zacc[mi][0];
            zsh[warpi * 128 + jl + 8] = zacc[mi][1];
        }
    }
    __syncthreads();
    if (tid < 128) {
        float z = zsh[tid] + zsh[128 + tid] + zsh[256 + tid] + zsh[384 + tid];
        g_Zp[(((size_t)b * NN) + j0 + tid) * ZSPLITS + isplit] = z;
    }
}

// ---------------------------------------------------------------------------
// Kernel 3: combine partial Z -> g_rZ = 1/Z
// ---------------------------------------------------------------------------
__global__ __launch_bounds__(256) void zcombine_kernel()
{
    int row = blockIdx.x * 256 + threadIdx.x;
    float z = 0.0f;
    #pragma unroll
    for (int p = 0; p < ZSPLITS; p++) z += g_Zp[row * ZSPLITS + p];
    g_rZ[row] = (z > 0.0f) ? 1.0f / z : 0.0f;
}

// ---------------------------------------------------------------------------
// Kernel 4: fused PV (R13, unchanged: register prefetch of next j-tile;
// empty-split blocks return early -- their g_part slots stay zero-initialized
// and are never dirtied, so reduce sees zeros deterministically).
// ---------------------------------------------------------------------------
#define PV_SMEM ((128*68 + 64*68 + 64*72 + 64*136) * 4)
__global__ __launch_bounds__(512) void pv_kernel()
{
    const int IT    = blockIdx.x;            // 0..15
    const int split = blockIdx.y;            // 0..7
    const int b     = blockIdx.z;
    const int n_jt  = 2 * IT + 2;
    const int chunk = (n_jt + SPLITS - 1) / SPLITS;
    const int jt0   = split * chunk;
    const int jt1   = min(n_jt, jt0 + chunk);

    extern __shared__ unsigned dynsm[];
    unsigned (*ks_)[68]  = (unsigned(*)[68])dynsm;                              // [i][h]
    unsigned (*qs_)[68]  = (unsigned(*)[68])(dynsm + 128*68);                   // [j][h]
    unsigned (*vs_)[72]  = (unsigned(*)[72])(dynsm + 128*68 + 64*68);           // [j][h]
    unsigned (*ps_)[136] = (unsigned(*)[136])(dynsm + 128*68 + 64*68 + 64*72);  // [j][i]

    const int tid = threadIdx.x;
    const int wid = tid >> 5, lane = tid & 31;
    const int group = lane >> 2, tig = lane & 3;
    const int warpj = wid >> 2;         // 0..3
    const int warpi = wid & 3;          // 0..3
    const int warp_m = wid >> 2;        // 0..3
    const int warp_n = wid & 3;         // 0..3
    const int i0 = IT * 128;

    const float* kp = g_k + ((size_t)b * NN + i0) * HH;
    #pragma unroll
    for (int e = 0; e < 4; e++) {
        int id = tid + e * 512;                    // 2048 float4s
        int r = id >> 4, c4 = id & 15;
        float4 k4 = *(const float4*)&kp[(size_t)r * HH + c4 * 4];
        ks_[r][c4*4+0]=f2tf(k4.x); ks_[r][c4*4+1]=f2tf(k4.y);
        ks_[r][c4*4+2]=f2tf(k4.z); ks_[r][c4*4+3]=f2tf(k4.w);
    }

    if (jt0 >= jt1) { return; }   // empty chunk: g_part slot stays zero (static init)

    float acc[2][2][4] = {};

    float4 qbuf[2], vbuf[2];
    float  rzbuf[2];
    {
        const int j0p = jt0 * 64;
        const float* qp = g_q + ((size_t)b * NN + j0p) * HH;
        #pragma unroll
        for (int e = 0; e < 2; e++) {
            int id = tid + e * 512;
            int r = id >> 4, c4 = id & 15;
            qbuf[e]  = *(const float4*)&qp[(size_t)r * HH + c4 * 4];
            rzbuf[e] = g_rZ[b * NN + j0p + r];
            vbuf[e]  = *(const float4*)&g_v[((size_t)b * NN + j0p + r) * HH + c4 * 4];
        }
    }

    for (int jt = jt0; jt < jt1; jt++) {
        const int j0 = jt * 64;
        __syncthreads();
        #pragma unroll
        for (int e = 0; e < 2; e++) {
            int id = tid + e * 512;
            int r = id >> 4, c4 = id & 15;
            float4 q4 = qbuf[e];
            qs_[r][c4*4+0]=f2tf(q4.x); qs_[r][c4*4+1]=f2tf(q4.y);
            qs_[r][c4*4+2]=f2tf(q4.z); qs_[r][c4*4+3]=f2tf(q4.w);
            float rz = rzbuf[e];
            float4 v = vbuf[e];
            vs_[r][c4*4+0] = f2tf(v.x * rz); vs_[r][c4*4+1] = f2tf(v.y * rz);
            vs_[r][c4*4+2] = f2tf(v.z * rz); vs_[r][c4*4+3] = f2tf(v.w * rz);
        }
        __syncthreads();

        if (jt + 1 < jt1) {
            const int j0n = (jt + 1) * 64;
            const float* qp = g_q + ((size_t)b * NN + j0n) * HH;
            #pragma unroll
            for (int e = 0; e < 2; e++) {
                int id = tid + e * 512;
                int r = id >> 4, c4 = id & 15;
                qbuf[e]  = *(const float4*)&qp[(size_t)r * HH + c4 * 4];
                rzbuf[e] = g_rZ[b * NN + j0n + r];
                vbuf[e]  = *(const float4*)&g_v[((size_t)b * NN + j0n + r) * HH + c4 * 4];
            }
        }

        float acc1[4][4] = {};
        #pragma unroll
        for (int kk = 0; kk < 8; kk++) {
            const int k = kk * 8;
            unsigned af[4];
            {
                int r = warpj * 16 + group;
                af[0] = qs_[r][k + tig];     af[1] = qs_[r + 8][k + tig];
                af[2] = qs_[r][k + tig + 4]; af[3] = qs_[r + 8][k + tig + 4];
            }
            unsigned bf[4][2];
            #pragma unroll
            for (int ni = 0; ni < 4; ni++) {
                int c = warpi * 32 + ni * 8 + group;
                bf[ni][0] = ks_[c][k + tig];
                bf[ni][1] = ks_[c][k + tig + 4];
            }
            #pragma unroll
            for (int ni = 0; ni < 4; ni++)
                mma8(acc1[ni], af[0], af[1], af[2], af[3], bf[ni][0], bf[ni][1]);
        }

        #pragma unroll
        for (int ni = 0; ni < 4; ni++) {
            int jl = warpj * 16 + group;
            int il = warpi * 32 + ni * 8 + 2 * tig;
            int jA = j0 + jl, iA = i0 + il;
            float v00 = acc1[ni][0], v01 = acc1[ni][1];
            float v10 = acc1[ni][2], v11 = acc1[ni][3];
            float e00 = (iA     < jA     || v00 == 0.0f) ? 0.0f : __expf(v00 * 0.125f);
            float e01 = (iA + 1 < jA     || v01 == 0.0f) ? 0.0f : __expf(v01 * 0.125f);
            float e10 = (iA     < jA + 8 || v10 == 0.0f) ? 0.0f : __expf(v10 * 0.125f);
            float e11 = (iA + 1 < jA + 8 || v11 == 0.0f) ? 0.0f : __expf(v11 * 0.125f);
            *(uint2*)&ps_[jl][il]     = make_uint2(f2tf(e00), f2tf(e01));
            *(uint2*)&ps_[jl + 8][il] = make_uint2(f2tf(e10), f2tf(e11));
        }
        __syncthreads();

        #pragma unroll
        for (int kk = 0; kk < 8; kk++) {
            const int k = kk * 8;
            unsigned af[2][4];
            #pragma unroll
            for (int mi = 0; mi < 2; mi++) {
                int iL = warp_m * 32 + mi * 16 + group;
                af[mi][0] = ps_[k + tig][iL];     af[mi][1] = ps_[k + tig][iL + 8];
                af[mi][2] = ps_[k + tig + 4][iL]; af[mi][3] = ps_[k + tig + 4][iL + 8];
            }
            unsigned bf[2][2];
            #pragma unroll
            for (int ni = 0; ni < 2; ni++) {
                int h = warp_n * 16 + ni * 8 + group;
                bf[ni][0] = vs_[k + tig][h];
                bf[ni][1] = vs_[k + tig + 4][h];
            }
            #pragma unroll
            for (int mi = 0; mi < 2; mi++)
                #pragma unroll
                for (int ni = 0; ni < 2; ni++)
                    mma8(acc[mi][ni], af[mi][0], af[mi][1], af[mi][2], af[mi][3],
                         bf[ni][0], bf[ni][1]);
        }
    }

    float* P = g_part[split];
    #pragma unroll
    for (int mi = 0; mi < 2; mi++) {
        #pragma unroll
        for (int ni = 0; ni < 2; ni++) {
            int iA = i0 + warp_m * 32 + mi * 16 + group;
            int h  = warp_n * 16 + ni * 8 + 2 * tig;
            *(float2*)&P[((size_t)b * NN + iA) * HH + h] =
                make_float2(acc[mi][ni][0], acc[mi][ni][1]);
            *(float2*)&P[((size_t)b * NN + iA + 8) * HH + h] =
                make_float2(acc[mi][ni][2], acc[mi][ni][3]);
        }
    }
}

// ---------------------------------------------------------------------------
// Kernel 5: reduce split-K partials
// ---------------------------------------------------------------------------
__global__ __launch_bounds__(256) void reduce_kernel(float* __restrict__ out)
{
    size_t idx = (size_t)blockIdx.x * 256 + threadIdx.x;
    float s = 0.0f;
    #pragma unroll
    for (int p = 0; p < SPLITS; p++) s += g_part[p][idx];
    out[idx] = s;
}

// ---------------------------------------------------------------------------
extern "C" void kernel_launch(void* const* d_in, const int* in_sizes, int n_in,
                              void* d_out, int out_size)
{
    const float* x  = (const float*)d_in[0];
    const float* Wq = (const float*)d_in[1];
    const float* bq = (const float*)d_in[2];
    const float* Wk = (const float*)d_in[3];
    const float* bk = (const float*)d_in[4];
    const float* Wv = (const float*)d_in[5];
    const float* bv = (const float*)d_in[6];
    float* out = (float*)d_out;

    static bool attrs_set = false;
    if (!attrs_set) {
        cudaFuncSetAttribute(zsum_kernel, cudaFuncAttributeMaxDynamicSharedMemorySize, ZS_SMEM);
        cudaFuncSetAttribute(pv_kernel,   cudaFuncAttributeMaxDynamicSharedMemorySize, PV_SMEM);
        attrs_set = true;
    }

    qkv_kernel<<<dim3(M_TOT / 64), 256>>>(x, Wq, bq, Wk, bk, Wv, bv);
    zsum_kernel<<<dim3(NN / 128, ZSPLITS, BB), 256, ZS_SMEM>>>();
    zcombine_kernel<<<M_TOT / 256, 256>>>();
    pv_kernel<<<dim3(NN / 128, SPLITS, BB), 512, PV_SMEM>>>();
    reduce_kernel<<<(M_TOT * HH) / 256, 256>>>(out);
}

// round 16
// speedup vs baseline: 1.4820x; 1.4820x over previous
#include <cuda_runtime.h>
#include <math.h>

#define BB 4
#define NN 2048
#define DD 1024
#define HH 64
#define M_TOT (BB*NN)
#define SPLITS 8
#define ZSPLITS 8

static __device__ float g_q[M_TOT*HH];
static __device__ float g_k[M_TOT*HH];
static __device__ float g_v[M_TOT*HH];
static __device__ float g_Zp[M_TOT*ZSPLITS];       // partial row sums
static __device__ float g_rZ[M_TOT];               // 1/rowsum
static __device__ float g_part[SPLITS][M_TOT*HH];  // split-K partials for PV

// ---------------------------------------------------------------------------
// TF32 helpers
// ---------------------------------------------------------------------------
__device__ __forceinline__ unsigned f2tf(float f) {
    unsigned u; asm("cvt.rna.tf32.f32 %0, %1;" : "=r"(u) : "f"(f)); return u;
}
__device__ __forceinline__ void mma8(float c[4],
                                     unsigned a0, unsigned a1, unsigned a2, unsigned a3,
                                     unsigned b0, unsigned b1) {
    asm volatile(
        "mma.sync.aligned.m16n8k8.row.col.f32.tf32.tf32.f32 "
        "{%0,%1,%2,%3}, {%4,%5,%6,%7}, {%8,%9}, {%0,%1,%2,%3};"
        : "+f"(c[0]), "+f"(c[1]), "+f"(c[2]), "+f"(c[3])
        : "r"(a0), "r"(a1), "r"(a2), "r"(a3), "r"(b0), "r"(b1));
}

// ---------------------------------------------------------------------------
// Kernel 1: fused QKV projection, tf32 MMA. x-tile-only register prefetch
// (8 regs; W tiles are cross-block broadcast -> L2-hot, left inline).
// ---------------------------------------------------------------------------
__global__ __launch_bounds__(256) void qkv_kernel(
    const float* __restrict__ x,
    const float* __restrict__ Wq, const float* __restrict__ bq,
    const float* __restrict__ Wk, const float* __restrict__ bk,
    const float* __restrict__ Wv, const float* __restrict__ bv)
{
    __shared__ unsigned as_[64][36];
    __shared__ unsigned bs_[32][200];

    const int tid = threadIdx.x;
    const int wid = tid >> 5, lane = tid & 31;
    const int group = lane >> 2, tig = lane & 3;
    const int warp_m = wid >> 2;
    const int warp_n = wid & 3;
    const int row0 = blockIdx.x * 64;

    float acc[2][6][4] = {};

    // x prefetch buffer only (2 float4 = 8 regs)
    float4 xbuf[2];
    #pragma unroll
    for (int e = 0; e < 2; e++) {
        int id = tid + e * 256;
        int r = id >> 3, c4 = id & 7;
        xbuf[e] = *(const float4*)&x[(size_t)(row0 + r) * DD + c4 * 4];
    }

    for (int kt = 0; kt < DD; kt += 32) {
        // ---- x tile from prefetched registers ----
        #pragma unroll
        for (int e = 0; e < 2; e++) {
            int id = tid + e * 256;
            int r = id >> 3, c4 = id & 7;
            float4 v = xbuf[e];
            as_[r][c4*4+0] = f2tf(v.x); as_[r][c4*4+1] = f2tf(v.y);
            as_[r][c4*4+2] = f2tf(v.z); as_[r][c4*4+3] = f2tf(v.w);
        }
        // ---- W tiles inline (L2-hot broadcast) ----
        #pragma unroll
        for (int p = 0; p < 3; p++) {
            const float* W = (p == 0) ? Wq : (p == 1) ? Wk : Wv;
            #pragma unroll
            for (int e = 0; e < 2; e++) {
                int id = tid + e * 256;
                int r = id >> 4, c4 = id & 15;
                float4 v = *(const float4*)&W[(size_t)(kt + r) * HH + c4 * 4];
                bs_[r][p*64 + c4*4+0] = f2tf(v.x); bs_[r][p*64 + c4*4+1] = f2tf(v.y);
                bs_[r][p*64 + c4*4+2] = f2tf(v.z); bs_[r][p*64 + c4*4+3] = f2tf(v.w);
            }
        }
        __syncthreads();

        // ---- prefetch next x tile (overlaps MMAs) ----
        if (kt + 32 < DD) {
            #pragma unroll
            for (int e = 0; e < 2; e++) {
                int id = tid + e * 256;
                int r = id >> 3, c4 = id & 7;
                xbuf[e] = *(const float4*)&x[(size_t)(row0 + r) * DD + (kt + 32) + c4 * 4];
            }
        }

        #pragma unroll
        for (int kk = 0; kk < 4; kk++) {
            const int k = kk * 8;
            unsigned af[2][4];
            #pragma unroll
            for (int mi = 0; mi < 2; mi++) {
                int r = warp_m * 32 + mi * 16 + group;
                af[mi][0] = as_[r][k + tig];     af[mi][1] = as_[r + 8][k + tig];
                af[mi][2] = as_[r][k + tig + 4]; af[mi][3] = as_[r + 8][k + tig + 4];
            }
            unsigned bf[6][2];
            #pragma unroll
            for (int ni = 0; ni < 6; ni++) {
                int c = warp_n * 48 + ni * 8 + group;
                bf[ni][0] = bs_[k + tig][c];
                bf[ni][1] = bs_[k + tig + 4][c];
            }
            #pragma unroll
            for (int mi = 0; mi < 2; mi++)
                #pragma unroll
                for (int ni = 0; ni < 6; ni++)
                    mma8(acc[mi][ni], af[mi][0], af[mi][1], af[mi][2], af[mi][3],
                         bf[ni][0], bf[ni][1]);
        }
        __syncthreads();
    }

    #pragma unroll
    for (int mi = 0; mi < 2; mi++) {
        int r = row0 + warp_m * 32 + mi * 16 + group;
        #pragma unroll
        for (int ni = 0; ni < 6; ni++) {
            int col = warp_n * 48 + ni * 8 + 2 * tig;
            int p = col >> 6, c = col & 63;
            const float* bias = (p == 0) ? bq : (p == 1) ? bk : bv;
            float* outp      = (p == 0) ? g_q : (p == 1) ? g_k : g_v;
            float b0 = bias[c], b1 = bias[c + 1];
            *(float2*)&outp[(size_t)r * HH + c] =
                make_float2(acc[mi][ni][0] + b0, acc[mi][ni][1] + b1);
            *(float2*)&outp[(size_t)(r + 8) * HH + c] =
                make_float2(acc[mi][ni][2] + b0, acc[mi][ni][3] + b1);
        }
    }
}

// ---------------------------------------------------------------------------
// Kernel 2: zsum (exact R13 version: inline K loads, no prefetch).
// Warps 2(j) x 4(i); warp tile 64j x 32i. isplit 8-way.
// ---------------------------------------------------------------------------
#define ZS_SMEM ((2 * 128 * 68 + 4 * 128) * 4)
__global__ __launch_bounds__(256) void zsum_kernel()
{
    const int tj = blockIdx.x, isplit = blockIdx.y, b = blockIdx.z;

    extern __shared__ unsigned dynsm[];
    unsigned (*qs_)[68] = (unsigned(*)[68])dynsm;              // [j][h]
    unsigned (*ks_)[68] = (unsigned(*)[68])(dynsm + 128 * 68); // [i][h]
    float* zsh = (float*)(dynsm + 2 * 128 * 68);               // [4 warpi][128 j]

    const int tid = threadIdx.x;
    const int wid = tid >> 5, lane = tid & 31;
    const int group = lane >> 2, tig = lane & 3;
    const int warpj = wid >> 2;         // 0..1 (64 j each)
    const int warpi = wid & 3;          // 0..3 (32 i each)
    const int j0 = tj * 128;

    const float* qp = g_q + ((size_t)b * NN + j0) * HH;
    #pragma unroll
    for (int e = 0; e < 8; e++) {
        int id = tid + e * 256;                    // 2048 float4s
        int r = id >> 4, c4 = id & 15;
        float4 q4 = *(const float4*)&qp[(size_t)r * HH + c4 * 4];
        qs_[r][c4*4+0]=f2tf(q4.x); qs_[r][c4*4+1]=f2tf(q4.y);
        qs_[r][c4*4+2]=f2tf(q4.z); qs_[r][c4*4+3]=f2tf(q4.w);
    }

    const int count = 16 - tj;
    const int chunk = (count + ZSPLITS - 1) / ZSPLITS;
    const int it0 = tj + isplit * chunk;
    const int it1 = min(16, it0 + chunk);

    float zacc[4][2] = {};

    for (int it = it0; it < it1; it++) {
        __syncthreads();       // protect ks_ (prior iter reads / qs_ stores on iter 0)
        const float* kp = g_k + ((size_t)b * NN + it * 128) * HH;
        #pragma unroll
        for (int e = 0; e < 8; e++) {
            int id = tid + e * 256;
            int r = id >> 4, c4 = id & 15;
            float4 k4 = *(const float4*)&kp[(size_t)r * HH + c4 * 4];
            ks_[r][c4*4+0]=f2tf(k4.x); ks_[r][c4*4+1]=f2tf(k4.y);
            ks_[r][c4*4+2]=f2tf(k4.z); ks_[r][c4*4+3]=f2tf(k4.w);
        }
        __syncthreads();

        float acc[4][4][4] = {};
        #pragma unroll
        for (int kk = 0; kk < 8; kk++) {
            const int k = kk * 8;
            unsigned af[4][4];
            #pragma unroll
            for (int mi = 0; mi < 4; mi++) {
                int r = warpj * 64 + mi * 16 + group;
                af[mi][0] = qs_[r][k + tig];     af[mi][1] = qs_[r + 8][k + tig];
                af[mi][2] = qs_[r][k + tig + 4]; af[mi][3] = qs_[r + 8][k + tig + 4];
            }
            unsigned bf[4][2];
            #pragma unroll
            for (int ni = 0; ni < 4; ni++) {
                int c = warpi * 32 + ni * 8 + group;
                bf[ni][0] = ks_[c][k + tig];
                bf[ni][1] = ks_[c][k + tig + 4];
            }
            #pragma unroll
            for (int mi = 0; mi < 4; mi++)
                #pragma unroll
                for (int ni = 0; ni < 4; ni++)
                    mma8(acc[mi][ni], af[mi][0], af[mi][1], af[mi][2], af[mi][3],
                         bf[ni][0], bf[ni][1]);
        }

        const int i0 = it * 128;
        #pragma unroll
        for (int mi = 0; mi < 4; mi++) {
            #pragma unroll
            for (int ni = 0; ni < 4; ni++) {
                int jA = j0 + warpj * 64 + mi * 16 + group;
                int iA = i0 + warpi * 32 + ni * 8 + 2 * tig;
                float v00 = acc[mi][ni][0], v01 = acc[mi][ni][1];
                float v10 = acc[mi][ni][2], v11 = acc[mi][ni][3];
                float e00 = (iA     < jA     || v00 == 0.0f) ? 0.0f : __expf(v00 * 0.125f);
                float e01 = (iA + 1 < jA     || v01 == 0.0f) ? 0.0f : __expf(v01 * 0.125f);
                float e10 = (iA     < jA + 8 || v10 == 0.0f) ? 0.0f : __expf(v10 * 0.125f);
                float e11 = (iA + 1 < jA + 8 || v11 == 0.0f) ? 0.0f : __expf(v11 * 0.125f);
                zacc[mi][0] += e00 + e01;
                zacc[mi][1] += e10 + e11;
            }
        }
    }

    #pragma unroll
    for (int mi = 0; mi < 4; mi++) {
        float s0 = zacc[mi][0], s1 = zacc[mi][1];
        s0 += __shfl_xor_sync(0xffffffffu, s0, 1);
        s0 += __shfl_xor_sync(0xffffffffu, s0, 2);
        s1 += __shfl_xor_sync(0xffffffffu, s1, 1);
        s1 += __shfl_xor_sync(0xffffffffu, s1, 2);
        zacc[mi][0] = s0; zacc[mi][1] = s1;
    }
    __syncthreads();
    if (tig == 0) {
        #pragma unroll
        for (int mi = 0; mi < 4; mi++) {
            int jl = warpj * 64 + mi * 16 + group;
            zsh[warpi * 128 + jl]     = zacc[mi][0];
            zsh[warpi * 128 + jl + 8] = zacc[mi][1];
        }
    }
    __syncthreads();
    if (tid < 128) {
        float z = zsh[tid] + zsh[128 + tid] + zsh[256 + tid] + zsh[384 + tid];
        g_Zp[(((size_t)b * NN) + j0 + tid) * ZSPLITS + isplit] = z;
    }
}

// ---------------------------------------------------------------------------
// Kernel 3: combine partial Z -> g_rZ = 1/Z
// ---------------------------------------------------------------------------
__global__ __launch_bounds__(256) void zcombine_kernel()
{
    int row = blockIdx.x * 256 + threadIdx.x;
    float z = 0.0f;
    #pragma unroll
    for (int p = 0; p < ZSPLITS; p++) z += g_Zp[row * ZSPLITS + p];
    g_rZ[row] = (z > 0.0f) ? 1.0f / z : 0.0f;
}

// ---------------------------------------------------------------------------
// Kernel 4: fused PV (exact R13: register prefetch of next j-tile; empty-split
// blocks return early -- g_part slots stay zero-initialized, never dirtied).
// ---------------------------------------------------------------------------
#define PV_SMEM ((128*68 + 64*68 + 64*72 + 64*136) * 4)
__global__ __launch_bounds__(512) void pv_kernel()
{
    const int IT    = blockIdx.x;            // 0..15
    const int split = blockIdx.y;            // 0..7
    const int b     = blockIdx.z;
    const int n_jt  = 2 * IT + 2;
    const int chunk = (n_jt + SPLITS - 1) / SPLITS;
    const int jt0   = split * chunk;
    const int jt1   = min(n_jt, jt0 + chunk);

    extern __shared__ unsigned dynsm[];
    unsigned (*ks_)[68]  = (unsigned(*)[68])dynsm;                              // [i][h]
    unsigned (*qs_)[68]  = (unsigned(*)[68])(dynsm + 128*68);                   // [j][h]
    unsigned (*vs_)[72]  = (unsigned(*)[72])(dynsm + 128*68 + 64*68);           // [j][h]
    unsigned (*ps_)[136] = (unsigned(*)[136])(dynsm + 128*68 + 64*68 + 64*72);  // [j][i]

    const int tid = threadIdx.x;
    const int wid = tid >> 5, lane = tid & 31;
    const int group = lane >> 2, tig = lane & 3;
    const int warpj = wid >> 2;         // 0..3
    const int warpi = wid & 3;          // 0..3
    const int warp_m = wid >> 2;        // 0..3
    const int warp_n = wid & 3;         // 0..3
    const int i0 = IT * 128;

    const float* kp = g_k + ((size_t)b * NN + i0) * HH;
    #pragma unroll
    for (int e = 0; e < 4; e++) {
        int id = tid + e * 512;                    // 2048 float4s
        int r = id >> 4, c4 = id & 15;
        float4 k4 = *(const float4*)&kp[(size_t)r * HH + c4 * 4];
        ks_[r][c4*4+0]=f2tf(k4.x); ks_[r][c4*4+1]=f2tf(k4.y);
        ks_[r][c4*4+2]=f2tf(k4.z); ks_[r][c4*4+3]=f2tf(k4.w);
    }

    if (jt0 >= jt1) { return; }   // empty chunk: g_part slot stays zero (static init)

    float acc[2][2][4] = {};

    float4 qbuf[2], vbuf[2];
    float  rzbuf[2];
    {
        const int j0p = jt0 * 64;
        const float* qp = g_q + ((size_t)b * NN + j0p) * HH;
        #pragma unroll
        for (int e = 0; e < 2; e++) {
            int id = tid + e * 512;
            int r = id >> 4, c4 = id & 15;
            qbuf[e]  = *(const float4*)&qp[(size_t)r * HH + c4 * 4];
            rzbuf[e] = g_rZ[b * NN + j0p + r];
            vbuf[e]  = *(const float4*)&g_v[((size_t)b * NN + j0p + r) * HH + c4 * 4];
        }
    }

    for (int jt = jt0; jt < jt1; jt++) {
        const int j0 = jt * 64;
        __syncthreads();
        #pragma unroll
        for (int e = 0; e < 2; e++) {
            int id = tid + e * 512;
            int r = id >> 4, c4 = id & 15;
            float4 q4 = qbuf[e];
            qs_[r][c4*4+0]=f2tf(q4.x); qs_[r][c4*4+1]=f2tf(q4.y);
            qs_[r][c4*4+2]=f2tf(q4.z); qs_[r][c4*4+3]=f2tf(q4.w);
            float rz = rzbuf[e];
            float4 v = vbuf[e];
            vs_[r][c4*4+0] = f2tf(v.x * rz); vs_[r][c4*4+1] = f2tf(v.y * rz);
            vs_[r][c4*4+2] = f2tf(v.z * rz); vs_[r][c4*4+3] = f2tf(v.w * rz);
        }
        __syncthreads();

        if (jt + 1 < jt1) {
            const int j0n = (jt + 1) * 64;
            const float* qp = g_q + ((size_t)b * NN + j0n) * HH;
            #pragma unroll
            for (int e = 0; e < 2; e++) {
                int id = tid + e * 512;
                int r = id >> 4, c4 = id & 15;
                qbuf[e]  = *(const float4*)&qp[(size_t)r * HH + c4 * 4];
                rzbuf[e] = g_rZ[b * NN + j0n + r];
                vbuf[e]  = *(const float4*)&g_v[((size_t)b * NN + j0n + r) * HH + c4 * 4];
            }
        }

        float acc1[4][4] = {};
        #pragma unroll
        for (int kk = 0; kk < 8; kk++) {
            const int k = kk * 8;
            unsigned af[4];
            {
                int r = warpj * 16 + group;
                af[0] = qs_[r][k + tig];     af[1] = qs_[r + 8][k + tig];
                af[2] = qs_[r][k + tig + 4]; af[3] = qs_[r + 8][k + tig + 4];
            }
            unsigned bf[4][2];
            #pragma unroll
            for (int ni = 0; ni < 4; ni++) {
                int c = warpi * 32 + ni * 8 + group;
                bf[ni][0] = ks_[c][k + tig];
                bf[ni][1] = ks_[c][k + tig + 4];
            }
            #pragma unroll
            for (int ni = 0; ni < 4; ni++)
                mma8(acc1[ni], af[0], af[1], af[2], af[3], bf[ni][0], bf[ni][1]);
        }

        #pragma unroll
        for (int ni = 0; ni < 4; ni++) {
            int jl = warpj * 16 + group;
            int il = warpi * 32 + ni * 8 + 2 * tig;
            int jA = j0 + jl, iA = i0 + il;
            float v00 = acc1[ni][0], v01 = acc1[ni][1];
            float v10 = acc1[ni][2], v11 = acc1[ni][3];
            float e00 = (iA     < jA     || v00 == 0.0f) ? 0.0f : __expf(v00 * 0.125f);
            float e01 = (iA + 1 < jA     || v01 == 0.0f) ? 0.0f : __expf(v01 * 0.125f);
            float e10 = (iA     < jA + 8 || v10 == 0.0f) ? 0.0f : __expf(v10 * 0.125f);
            float e11 = (iA + 1 < jA + 8 || v11 == 0.0f) ? 0.0f : __expf(v11 * 0.125f);
            *(uint2*)&ps_[jl][il]     = make_uint2(f2tf(e00), f2tf(e01));
            *(uint2*)&ps_[jl + 8][il] = make_uint2(f2tf(e10), f2tf(e11));
        }
        __syncthreads();

        #pragma unroll
        for (int kk = 0; kk < 8; kk++) {
            const int k = kk * 8;
            unsigned af[2][4];
            #pragma unroll
            for (int mi = 0; mi < 2; mi++) {
                int iL = warp_m * 32 + mi * 16 + group;
                af[mi][0] = ps_[k + tig][iL];     af[mi][1] = ps_[k + tig][iL + 8];
                af[mi][2] = ps_[k + tig + 4][iL]; af[mi][3] = ps_[k + tig + 4][iL + 8];
            }
            unsigned bf[2][2];
            #pragma unroll
            for (int ni = 0; ni < 2; ni++) {
                int h = warp_n * 16 + ni * 8 + group;
                bf[ni][0] = vs_[k + tig][h];
                bf[ni][1] = vs_[k + tig + 4][h];
            }
            #pragma unroll
            for (int mi = 0; mi < 2; mi++)
                #pragma unroll
                for (int ni = 0; ni < 2; ni++)
                    mma8(acc[mi][ni], af[mi][0], af[mi][1], af[mi][2], af[mi][3],
                         bf[ni][0], bf[ni][1]);
        }
    }

    float* P = g_part[split];
    #pragma unroll
    for (int mi = 0; mi < 2; mi++) {
        #pragma unroll
        for (int ni = 0; ni < 2; ni++) {
            int iA = i0 + warp_m * 32 + mi * 16 + group;
            int h  = warp_n * 16 + ni * 8 + 2 * tig;
            *(float2*)&P[((size_t)b * NN + iA) * HH + h] =
                make_float2(acc[mi][ni][0], acc[mi][ni][1]);
            *(float2*)&P[((size_t)b * NN + iA + 8) * HH + h] =
                make_float2(acc[mi][ni][2], acc[mi][ni][3]);
        }
    }
}

// ---------------------------------------------------------------------------
// Kernel 5: reduce split-K partials
// ---------------------------------------------------------------------------
__global__ __launch_bounds__(256) void reduce_kernel(float* __restrict__ out)
{
    size_t idx = (size_t)blockIdx.x * 256 + threadIdx.x;
    float s = 0.0f;
    #pragma unroll
    for (int p = 0; p < SPLITS; p++) s += g_part[p][idx];
    out[idx] = s;
}

// ---------------------------------------------------------------------------
extern "C" void kernel_launch(void* const* d_in, const int* in_sizes, int n_in,
                              void* d_out, int out_size)
{
    const float* x  = (const float*)d_in[0];
    const float* Wq = (const float*)d_in[1];
    const float* bq = (const float*)d_in[2];
    const float* Wk = (const float*)d_in[3];
    const float* bk = (const float*)d_in[4];
    const float* Wv = (const float*)d_in[5];
    const float* bv = (const float*)d_in[6];
    float* out = (float*)d_out;

    static bool attrs_set = false;
    if (!attrs_set) {
        cudaFuncSetAttribute(zsum_kernel, cudaFuncAttributeMaxDynamicSharedMemorySize, ZS_SMEM);
        cudaFuncSetAttribute(pv_kernel,   cudaFuncAttributeMaxDynamicSharedMemorySize, PV_SMEM);
        attrs_set = true;
    }

    qkv_kernel<<<dim3(M_TOT / 64), 256>>>(x, Wq, bq, Wk, bk, Wv, bv);
    zsum_kernel<<<dim3(NN / 128, ZSPLITS, BB), 256, ZS_SMEM>>>();
    zcombine_kernel<<<M_TOT / 256, 256>>>();
    pv_kernel<<<dim3(NN / 128, SPLITS, BB), 512, PV_SMEM>>>();
    reduce_kernel<<<(M_TOT * HH) / 256, 256>>>(out);
}